// round 13
// baseline (speedup 1.0000x reference)
#include <cuda_runtime.h>
#include <cuda_bf16.h>
#include <cstdint>

#define HIDDEN 4096
#define RANK   4
#define BATCH  4096
#define DELTA  1.0f

#define BM 128
#define BN 128
#define BK 32
#define NK (HIDDEN / BK)       // 128 k-iterations
#define ASTRIDE 36             // 32 + 4 pad  -> conflict-free A frag loads
#define BSTRIDE 136            // 128 + 8 pad -> conflict-free B frag loads
#define A_STAGE (BM * ASTRIDE) // 4608 floats
#define B_STAGE (BK * BSTRIDE) // 4352 floats
#define SMEM_FLOATS (2 * A_STAGE + 2 * B_STAGE)   // 17920
#define SMEM_BYTES  (SMEM_FLOATS * 4)             // 71680

// scratch for hq = h @ q_vec  [BATCH, RANK]
__device__ float g_hq[BATCH * RANK];

// ---------------------------------------------------------------------------
// helpers
// ---------------------------------------------------------------------------
__device__ __forceinline__ uint32_t f2tf(float x) {
    uint32_t r;
    asm("cvt.rna.tf32.f32 %0, %1;" : "=r"(r) : "f"(x));
    return r;
}

__device__ __forceinline__ void cp16(uint32_t saddr, const float* g) {
    asm volatile("cp.async.cg.shared.global [%0], [%1], 16;" :: "r"(saddr), "l"(g));
}

__device__ __forceinline__ void mma_tf32(float* c, const uint32_t* a, const uint32_t* b) {
    asm volatile(
        "mma.sync.aligned.m16n8k8.row.col.f32.tf32.tf32.f32 "
        "{%0,%1,%2,%3}, {%4,%5,%6,%7}, {%8,%9}, {%0,%1,%2,%3};"
        : "+f"(c[0]), "+f"(c[1]), "+f"(c[2]), "+f"(c[3])
        : "r"(a[0]), "r"(a[1]), "r"(a[2]), "r"(a[3]), "r"(b[0]), "r"(b[1]));
}

// ---------------------------------------------------------------------------
// hq[b][r] = sum_n h[b][n] * q[n][r]
// ---------------------------------------------------------------------------
__global__ void __launch_bounds__(256) hq_kernel(const float* __restrict__ H,
                                                 const float* __restrict__ Q) {
    int b = blockIdx.x;
    const float* hr = H + (size_t)b * HIDDEN;
    float a0 = 0.f, a1 = 0.f, a2 = 0.f, a3 = 0.f;
    for (int n = threadIdx.x; n < HIDDEN; n += 256) {
        float hv = __ldg(hr + n);
        float4 qv = __ldg(((const float4*)Q) + n);
        a0 += hv * qv.x; a1 += hv * qv.y; a2 += hv * qv.z; a3 += hv * qv.w;
    }
    #pragma unroll
    for (int off = 16; off; off >>= 1) {
        a0 += __shfl_xor_sync(0xFFFFFFFFu, a0, off);
        a1 += __shfl_xor_sync(0xFFFFFFFFu, a1, off);
        a2 += __shfl_xor_sync(0xFFFFFFFFu, a2, off);
        a3 += __shfl_xor_sync(0xFFFFFFFFu, a3, off);
    }
    __shared__ float red[8][4];
    int wid = threadIdx.x >> 5;
    if ((threadIdx.x & 31) == 0) {
        red[wid][0] = a0; red[wid][1] = a1; red[wid][2] = a2; red[wid][3] = a3;
    }
    __syncthreads();
    if (threadIdx.x < 4) {
        float s = 0.f;
        #pragma unroll
        for (int w = 0; w < 8; w++) s += red[w][threadIdx.x];
        g_hq[b * 4 + threadIdx.x] = s;
    }
}

// ---------------------------------------------------------------------------
// fused GEMM: Out = X @ Bm  + H*(1 + DELTA*a) + DELTA*(g_hq @ P^T)
//   X  [BATCH, HIDDEN]  row-major  (the "x" input)
//   Bm [HIDDEN, HIDDEN] row-major  (b_mat; k rows, n cols)
// block tile 128x128x32, 8 warps (2 m x 4 n), warp tile 64x32,
// m16n8k8 tf32 mma, double-buffered cp.async
// ---------------------------------------------------------------------------
__global__ void __launch_bounds__(256) gemm_fused_kernel(
    const float* __restrict__ X, const float* __restrict__ Bm,
    const float* __restrict__ H, const float* __restrict__ Ad,
    const float* __restrict__ P, float* __restrict__ Out)
{
    extern __shared__ float smem[];
    const uint32_t smem_u32 = (uint32_t)__cvta_generic_to_shared(smem);

    const int tid  = threadIdx.x;
    const int lane = tid & 31;
    const int wid  = tid >> 5;
    const int wm   = wid >> 2;        // 0..1   (64 rows each)
    const int wn   = wid & 3;         // 0..3   (32 cols each)
    const int gid  = lane >> 2;       // 0..7
    const int tig  = lane & 3;        // 0..3

    const int bm0 = blockIdx.y * BM;
    const int bn0 = blockIdx.x * BN;

    // ---- tile loader (cp.async) ----
    auto load_tiles = [&](int kt, int st) {
        #pragma unroll
        for (int i = 0; i < 4; i++) {
            int slot = tid + i * 256;          // 1024 float4 slots for A
            int arow = slot >> 3;              // 8 float4 per 32-float row
            int ac4  = slot & 7;
            cp16(smem_u32 + (uint32_t)(st * A_STAGE + arow * ASTRIDE + ac4 * 4) * 4u,
                 X + (size_t)(bm0 + arow) * HIDDEN + kt * BK + ac4 * 4);
        }
        #pragma unroll
        for (int i = 0; i < 4; i++) {
            int slot = tid + i * 256;          // 1024 float4 slots for B
            int brow = slot >> 5;              // 32 float4 per 128-float row
            int bc4  = slot & 31;
            cp16(smem_u32 + (uint32_t)(2 * A_STAGE + st * B_STAGE + brow * BSTRIDE + bc4 * 4) * 4u,
                 Bm + (size_t)(kt * BK + brow) * HIDDEN + bn0 + bc4 * 4);
        }
        asm volatile("cp.async.commit_group;");
    };

    float c[4][4][4];
    #pragma unroll
    for (int i = 0; i < 4; i++)
        #pragma unroll
        for (int j = 0; j < 4; j++)
            #pragma unroll
            for (int k = 0; k < 4; k++) c[i][j][k] = 0.f;

    load_tiles(0, 0);

    for (int kt = 0; kt < NK; kt++) {
        const int cur = kt & 1;
        if (kt + 1 < NK) {
            load_tiles(kt + 1, cur ^ 1);
            asm volatile("cp.async.wait_group 1;");
        } else {
            asm volatile("cp.async.wait_group 0;");
        }
        __syncthreads();

        const float* as = smem + cur * A_STAGE;
        const float* bs = smem + 2 * A_STAGE + cur * B_STAGE;

        #pragma unroll
        for (int kk = 0; kk < 4; kk++) {
            const int k0 = kk * 8;
            uint32_t af[4][4], bf[4][2];
            #pragma unroll
            for (int i = 0; i < 4; i++) {
                const int r = wm * 64 + i * 16 + gid;
                af[i][0] = f2tf(as[(r    ) * ASTRIDE + k0 + tig    ]);
                af[i][1] = f2tf(as[(r + 8) * ASTRIDE + k0 + tig    ]);
                af[i][2] = f2tf(as[(r    ) * ASTRIDE + k0 + tig + 4]);
                af[i][3] = f2tf(as[(r + 8) * ASTRIDE + k0 + tig + 4]);
            }
            #pragma unroll
            for (int j = 0; j < 4; j++) {
                const int cc = wn * 32 + j * 8 + gid;
                bf[j][0] = f2tf(bs[(k0 + tig    ) * BSTRIDE + cc]);
                bf[j][1] = f2tf(bs[(k0 + tig + 4) * BSTRIDE + cc]);
            }
            #pragma unroll
            for (int i = 0; i < 4; i++)
                #pragma unroll
                for (int j = 0; j < 4; j++)
                    mma_tf32(c[i][j], af[i], bf[j]);
        }
        __syncthreads();
    }

    // ---- fused epilogue: out = DELTA*acc + h*(1+DELTA*a) + DELTA*(hq . p) ----
    #pragma unroll
    for (int i = 0; i < 4; i++) {
        const int r0 = bm0 + wm * 64 + i * 16 + gid;
        const int r1 = r0 + 8;
        const float4 hq0 = *(const float4*)(g_hq + r0 * 4);
        const float4 hq1 = *(const float4*)(g_hq + r1 * 4);
        #pragma unroll
        for (int j = 0; j < 4; j++) {
            const int c0 = bn0 + wn * 32 + j * 8 + 2 * tig;
            const float2 ad = *(const float2*)(Ad + c0);
            const float4 p0 = *(const float4*)(P + (size_t)c0 * 4);
            const float4 p1 = *(const float4*)(P + (size_t)(c0 + 1) * 4);

            const float lr00 = hq0.x * p0.x + hq0.y * p0.y + hq0.z * p0.z + hq0.w * p0.w;
            const float lr01 = hq0.x * p1.x + hq0.y * p1.y + hq0.z * p1.z + hq0.w * p1.w;
            const float lr10 = hq1.x * p0.x + hq1.y * p0.y + hq1.z * p0.z + hq1.w * p0.w;
            const float lr11 = hq1.x * p1.x + hq1.y * p1.y + hq1.z * p1.z + hq1.w * p1.w;

            const float2 h0 = *(const float2*)(H + (size_t)r0 * HIDDEN + c0);
            const float2 h1 = *(const float2*)(H + (size_t)r1 * HIDDEN + c0);

            float2 o0, o1;
            o0.x = DELTA * c[i][j][0] + h0.x * (1.f + DELTA * ad.x) + DELTA * lr00;
            o0.y = DELTA * c[i][j][1] + h0.y * (1.f + DELTA * ad.y) + DELTA * lr01;
            o1.x = DELTA * c[i][j][2] + h1.x * (1.f + DELTA * ad.x) + DELTA * lr10;
            o1.y = DELTA * c[i][j][3] + h1.y * (1.f + DELTA * ad.y) + DELTA * lr11;

            *(float2*)(Out + (size_t)r0 * HIDDEN + c0) = o0;
            *(float2*)(Out + (size_t)r1 * HIDDEN + c0) = o1;
        }
    }
}

// ---------------------------------------------------------------------------
// launch
// ---------------------------------------------------------------------------
extern "C" void kernel_launch(void* const* d_in, const int* in_sizes, int n_in,
                              void* d_out, int out_size) {
    const float* h  = (const float*)d_in[0];   // [BATCH, HIDDEN]
    const float* x  = (const float*)d_in[1];   // [BATCH, HIDDEN]
    const float* a  = (const float*)d_in[2];   // [HIDDEN]
    const float* p  = (const float*)d_in[3];   // [HIDDEN, RANK]
    const float* q  = (const float*)d_in[4];   // [HIDDEN, RANK]
    const float* bm = (const float*)d_in[5];   // [HIDDEN, HIDDEN]
    float* out = (float*)d_out;

    // hq = h @ q   -> g_hq scratch
    hq_kernel<<<BATCH, 256>>>(h, q);

    // fused GEMM + epilogue
    static bool attr_set = false;
    if (!attr_set) {
        cudaFuncSetAttribute(gemm_fused_kernel,
                             cudaFuncAttributeMaxDynamicSharedMemorySize, SMEM_BYTES);
        attr_set = true;
    }
    dim3 grid(HIDDEN / BN, BATCH / BM);  // (32, 32)
    gemm_fused_kernel<<<grid, 256, SMEM_BYTES>>>(x, bm, h, a, p, out);
}

// round 14
// speedup vs baseline: 1.0007x; 1.0007x over previous
#include <cuda_runtime.h>
#include <cuda_bf16.h>
#include <cstdint>

#define HIDDEN 4096
#define RANK   4
#define BATCH  4096
#define DELTA  1.0f

#define BM 128
#define BN 128
#define BK 32
#define NK (HIDDEN / BK)       // 128 k-iterations
#define ASTRIDE 36             // 32 + 4 pad  -> conflict-free A frag loads
#define BSTRIDE 136            // 128 + 8 pad -> conflict-free B frag loads
#define A_STAGE (BM * ASTRIDE) // 4608 floats
#define B_STAGE (BK * BSTRIDE) // 4352 floats
#define SMEM_FLOATS (2 * A_STAGE + 2 * B_STAGE)   // 17920
#define SMEM_BYTES  (SMEM_FLOATS * 4)             // 71680

// scratch for hq = h @ q_vec  [BATCH, RANK]
__device__ float g_hq[BATCH * RANK];

// ---------------------------------------------------------------------------
// helpers
// ---------------------------------------------------------------------------
__device__ __forceinline__ uint32_t f2tf(float x) {
    uint32_t r;
    asm("cvt.rna.tf32.f32 %0, %1;" : "=r"(r) : "f"(x));
    return r;
}

__device__ __forceinline__ void cp16(uint32_t saddr, const float* g) {
    asm volatile("cp.async.cg.shared.global [%0], [%1], 16;" :: "r"(saddr), "l"(g));
}

__device__ __forceinline__ void mma_tf32(float* c, const uint32_t* a, const uint32_t* b) {
    asm volatile(
        "mma.sync.aligned.m16n8k8.row.col.f32.tf32.tf32.f32 "
        "{%0,%1,%2,%3}, {%4,%5,%6,%7}, {%8,%9}, {%0,%1,%2,%3};"
        : "+f"(c[0]), "+f"(c[1]), "+f"(c[2]), "+f"(c[3])
        : "r"(a[0]), "r"(a[1]), "r"(a[2]), "r"(a[3]), "r"(b[0]), "r"(b[1]));
}

// ---------------------------------------------------------------------------
// hq[b][r] = sum_n h[b][n] * q[n][r]
// ---------------------------------------------------------------------------
__global__ void __launch_bounds__(256) hq_kernel(const float* __restrict__ H,
                                                 const float* __restrict__ Q) {
    int b = blockIdx.x;
    const float* hr = H + (size_t)b * HIDDEN;
    float a0 = 0.f, a1 = 0.f, a2 = 0.f, a3 = 0.f;
    for (int n = threadIdx.x; n < HIDDEN; n += 256) {
        float hv = __ldg(hr + n);
        float4 qv = __ldg(((const float4*)Q) + n);
        a0 += hv * qv.x; a1 += hv * qv.y; a2 += hv * qv.z; a3 += hv * qv.w;
    }
    #pragma unroll
    for (int off = 16; off; off >>= 1) {
        a0 += __shfl_xor_sync(0xFFFFFFFFu, a0, off);
        a1 += __shfl_xor_sync(0xFFFFFFFFu, a1, off);
        a2 += __shfl_xor_sync(0xFFFFFFFFu, a2, off);
        a3 += __shfl_xor_sync(0xFFFFFFFFu, a3, off);
    }
    __shared__ float red[8][4];
    int wid = threadIdx.x >> 5;
    if ((threadIdx.x & 31) == 0) {
        red[wid][0] = a0; red[wid][1] = a1; red[wid][2] = a2; red[wid][3] = a3;
    }
    __syncthreads();
    if (threadIdx.x < 4) {
        float s = 0.f;
        #pragma unroll
        for (int w = 0; w < 8; w++) s += red[w][threadIdx.x];
        g_hq[b * 4 + threadIdx.x] = s;
    }
}

// ---------------------------------------------------------------------------
// fused GEMM: Out = X @ Bm  + H*(1 + DELTA*a) + DELTA*(g_hq @ P^T)
//   X  [BATCH, HIDDEN]  row-major  (the "x" input)
//   Bm [HIDDEN, HIDDEN] row-major  (b_mat; k rows, n cols)
// block tile 128x128x32, 8 warps (2 m x 4 n), warp tile 64x32,
// m16n8k8 tf32 mma, double-buffered cp.async
// ---------------------------------------------------------------------------
__global__ void __launch_bounds__(256) gemm_fused_kernel(
    const float* __restrict__ X, const float* __restrict__ Bm,
    const float* __restrict__ H, const float* __restrict__ Ad,
    const float* __restrict__ P, float* __restrict__ Out)
{
    extern __shared__ float smem[];
    const uint32_t smem_u32 = (uint32_t)__cvta_generic_to_shared(smem);

    const int tid  = threadIdx.x;
    const int lane = tid & 31;
    const int wid  = tid >> 5;
    const int wm   = wid >> 2;        // 0..1   (64 rows each)
    const int wn   = wid & 3;         // 0..3   (32 cols each)
    const int gid  = lane >> 2;       // 0..7
    const int tig  = lane & 3;        // 0..3

    const int bm0 = blockIdx.y * BM;
    const int bn0 = blockIdx.x * BN;

    // ---- tile loader (cp.async) ----
    auto load_tiles = [&](int kt, int st) {
        #pragma unroll
        for (int i = 0; i < 4; i++) {
            int slot = tid + i * 256;          // 1024 float4 slots for A
            int arow = slot >> 3;              // 8 float4 per 32-float row
            int ac4  = slot & 7;
            cp16(smem_u32 + (uint32_t)(st * A_STAGE + arow * ASTRIDE + ac4 * 4) * 4u,
                 X + (size_t)(bm0 + arow) * HIDDEN + kt * BK + ac4 * 4);
        }
        #pragma unroll
        for (int i = 0; i < 4; i++) {
            int slot = tid + i * 256;          // 1024 float4 slots for B
            int brow = slot >> 5;              // 32 float4 per 128-float row
            int bc4  = slot & 31;
            cp16(smem_u32 + (uint32_t)(2 * A_STAGE + st * B_STAGE + brow * BSTRIDE + bc4 * 4) * 4u,
                 Bm + (size_t)(kt * BK + brow) * HIDDEN + bn0 + bc4 * 4);
        }
        asm volatile("cp.async.commit_group;");
    };

    float c[4][4][4];
    #pragma unroll
    for (int i = 0; i < 4; i++)
        #pragma unroll
        for (int j = 0; j < 4; j++)
            #pragma unroll
            for (int k = 0; k < 4; k++) c[i][j][k] = 0.f;

    load_tiles(0, 0);

    for (int kt = 0; kt < NK; kt++) {
        const int cur = kt & 1;
        if (kt + 1 < NK) {
            load_tiles(kt + 1, cur ^ 1);
            asm volatile("cp.async.wait_group 1;");
        } else {
            asm volatile("cp.async.wait_group 0;");
        }
        __syncthreads();

        const float* as = smem + cur * A_STAGE;
        const float* bs = smem + 2 * A_STAGE + cur * B_STAGE;

        #pragma unroll
        for (int kk = 0; kk < 4; kk++) {
            const int k0 = kk * 8;
            uint32_t af[4][4], bf[4][2];
            #pragma unroll
            for (int i = 0; i < 4; i++) {
                const int r = wm * 64 + i * 16 + gid;
                af[i][0] = f2tf(as[(r    ) * ASTRIDE + k0 + tig    ]);
                af[i][1] = f2tf(as[(r + 8) * ASTRIDE + k0 + tig    ]);
                af[i][2] = f2tf(as[(r    ) * ASTRIDE + k0 + tig + 4]);
                af[i][3] = f2tf(as[(r + 8) * ASTRIDE + k0 + tig + 4]);
            }
            #pragma unroll
            for (int j = 0; j < 4; j++) {
                const int cc = wn * 32 + j * 8 + gid;
                bf[j][0] = f2tf(bs[(k0 + tig    ) * BSTRIDE + cc]);
                bf[j][1] = f2tf(bs[(k0 + tig + 4) * BSTRIDE + cc]);
            }
            #pragma unroll
            for (int i = 0; i < 4; i++)
                #pragma unroll
                for (int j = 0; j < 4; j++)
                    mma_tf32(c[i][j], af[i], bf[j]);
        }
        __syncthreads();
    }

    // ---- fused epilogue: out = DELTA*acc + h*(1+DELTA*a) + DELTA*(hq . p) ----
    #pragma unroll
    for (int i = 0; i < 4; i++) {
        const int r0 = bm0 + wm * 64 + i * 16 + gid;
        const int r1 = r0 + 8;
        const float4 hq0 = *(const float4*)(g_hq + r0 * 4);
        const float4 hq1 = *(const float4*)(g_hq + r1 * 4);
        #pragma unroll
        for (int j = 0; j < 4; j++) {
            const int c0 = bn0 + wn * 32 + j * 8 + 2 * tig;
            const float2 ad = *(const float2*)(Ad + c0);
            const float4 p0 = *(const float4*)(P + (size_t)c0 * 4);
            const float4 p1 = *(const float4*)(P + (size_t)(c0 + 1) * 4);

            const float lr00 = hq0.x * p0.x + hq0.y * p0.y + hq0.z * p0.z + hq0.w * p0.w;
            const float lr01 = hq0.x * p1.x + hq0.y * p1.y + hq0.z * p1.z + hq0.w * p1.w;
            const float lr10 = hq1.x * p0.x + hq1.y * p0.y + hq1.z * p0.z + hq1.w * p0.w;
            const float lr11 = hq1.x * p1.x + hq1.y * p1.y + hq1.z * p1.z + hq1.w * p1.w;

            const float2 h0 = *(const float2*)(H + (size_t)r0 * HIDDEN + c0);
            const float2 h1 = *(const float2*)(H + (size_t)r1 * HIDDEN + c0);

            float2 o0, o1;
            o0.x = DELTA * c[i][j][0] + h0.x * (1.f + DELTA * ad.x) + DELTA * lr00;
            o0.y = DELTA * c[i][j][1] + h0.y * (1.f + DELTA * ad.y) + DELTA * lr01;
            o1.x = DELTA * c[i][j][2] + h1.x * (1.f + DELTA * ad.x) + DELTA * lr10;
            o1.y = DELTA * c[i][j][3] + h1.y * (1.f + DELTA * ad.y) + DELTA * lr11;

            *(float2*)(Out + (size_t)r0 * HIDDEN + c0) = o0;
            *(float2*)(Out + (size_t)r1 * HIDDEN + c0) = o1;
        }
    }
}

// ---------------------------------------------------------------------------
// launch
// ---------------------------------------------------------------------------
extern "C" void kernel_launch(void* const* d_in, const int* in_sizes, int n_in,
                              void* d_out, int out_size) {
    const float* h  = (const float*)d_in[0];   // [BATCH, HIDDEN]
    const float* x  = (const float*)d_in[1];   // [BATCH, HIDDEN]
    const float* a  = (const float*)d_in[2];   // [HIDDEN]
    const float* p  = (const float*)d_in[3];   // [HIDDEN, RANK]
    const float* q  = (const float*)d_in[4];   // [HIDDEN, RANK]
    const float* bm = (const float*)d_in[5];   // [HIDDEN, HIDDEN]
    float* out = (float*)d_out;

    // hq = h @ q   -> g_hq scratch
    hq_kernel<<<BATCH, 256>>>(h, q);

    // fused GEMM + epilogue
    static bool attr_set = false;
    if (!attr_set) {
        cudaFuncSetAttribute(gemm_fused_kernel,
                             cudaFuncAttributeMaxDynamicSharedMemorySize, SMEM_BYTES);
        attr_set = true;
    }
    dim3 grid(HIDDEN / BN, BATCH / BM);  // (32, 32)
    gemm_fused_kernel<<<grid, 256, SMEM_BYTES>>>(x, bm, h, a, p, out);
}

// round 15
// speedup vs baseline: 1.3005x; 1.2997x over previous
#include <cuda_runtime.h>
#include <cuda_bf16.h>
#include <cstdint>

#define HIDDEN 4096
#define RANK   4
#define BATCH  4096
#define DELTA  1.0f

#define BM 128
#define BN 128
#define BK 32
#define NK (HIDDEN / BK)       // 128 k-iterations
#define STAGES 3
#define ASTRIDE 36             // 32 + 4 pad  -> conflict-free A frag loads
#define BSTRIDE 136            // 128 + 8 pad -> conflict-free B frag loads
#define A_STAGE (BM * ASTRIDE) // 4608 floats
#define B_STAGE (BK * BSTRIDE) // 4352 floats
#define SMEM_FLOATS (STAGES * (A_STAGE + B_STAGE))   // 26880
#define SMEM_BYTES  (SMEM_FLOATS * 4)                // 107520

// scratch for hq = h @ q_vec  [BATCH, RANK]
__device__ float g_hq[BATCH * RANK];

// ---------------------------------------------------------------------------
// helpers
// ---------------------------------------------------------------------------
__device__ __forceinline__ void cp16(uint32_t saddr, const float* g) {
    asm volatile("cp.async.cg.shared.global [%0], [%1], 16;" :: "r"(saddr), "l"(g));
}

// NOTE: no cvt.rna.tf32 — HMMA.TF32 truncates the low mantissa bits of fp32
// register operands in hardware (Triton allow_tf32 relies on the same).
__device__ __forceinline__ void mma_tf32(float* c, const uint32_t* a, const uint32_t* b) {
    asm volatile(
        "mma.sync.aligned.m16n8k8.row.col.f32.tf32.tf32.f32 "
        "{%0,%1,%2,%3}, {%4,%5,%6,%7}, {%8,%9}, {%0,%1,%2,%3};"
        : "+f"(c[0]), "+f"(c[1]), "+f"(c[2]), "+f"(c[3])
        : "r"(a[0]), "r"(a[1]), "r"(a[2]), "r"(a[3]), "r"(b[0]), "r"(b[1]));
}

// ---------------------------------------------------------------------------
// hq[b][r] = sum_n h[b][n] * q[n][r]
// ---------------------------------------------------------------------------
__global__ void __launch_bounds__(256) hq_kernel(const float* __restrict__ H,
                                                 const float* __restrict__ Q) {
    int b = blockIdx.x;
    const float* hr = H + (size_t)b * HIDDEN;
    float a0 = 0.f, a1 = 0.f, a2 = 0.f, a3 = 0.f;
    for (int n = threadIdx.x; n < HIDDEN; n += 256) {
        float hv = __ldg(hr + n);
        float4 qv = __ldg(((const float4*)Q) + n);
        a0 += hv * qv.x; a1 += hv * qv.y; a2 += hv * qv.z; a3 += hv * qv.w;
    }
    #pragma unroll
    for (int off = 16; off; off >>= 1) {
        a0 += __shfl_xor_sync(0xFFFFFFFFu, a0, off);
        a1 += __shfl_xor_sync(0xFFFFFFFFu, a1, off);
        a2 += __shfl_xor_sync(0xFFFFFFFFu, a2, off);
        a3 += __shfl_xor_sync(0xFFFFFFFFu, a3, off);
    }
    __shared__ float red[8][4];
    int wid = threadIdx.x >> 5;
    if ((threadIdx.x & 31) == 0) {
        red[wid][0] = a0; red[wid][1] = a1; red[wid][2] = a2; red[wid][3] = a3;
    }
    __syncthreads();
    if (threadIdx.x < 4) {
        float s = 0.f;
        #pragma unroll
        for (int w = 0; w < 8; w++) s += red[w][threadIdx.x];
        g_hq[b * 4 + threadIdx.x] = s;
    }
}

// ---------------------------------------------------------------------------
// fused GEMM: Out = X @ Bm + H*(1 + DELTA*a) + DELTA*(g_hq @ P^T)
// block tile 128x128x32, 8 warps (2m x 4n), warp tile 64x32,
// m16n8k8 tf32 mma, 3-stage cp.async pipeline, ONE syncthreads per k-tile,
// 2 CTAs/SM.
// ---------------------------------------------------------------------------
__global__ void __launch_bounds__(256, 2) gemm_fused_kernel(
    const float* __restrict__ X, const float* __restrict__ Bm,
    const float* __restrict__ H, const float* __restrict__ Ad,
    const float* __restrict__ P, float* __restrict__ Out)
{
    extern __shared__ float smem[];
    const uint32_t smem_u32 = (uint32_t)__cvta_generic_to_shared(smem);

    const int tid  = threadIdx.x;
    const int lane = tid & 31;
    const int wid  = tid >> 5;
    const int wm   = wid >> 2;        // 0..1   (64 rows each)
    const int wn   = wid & 3;         // 0..3   (32 cols each)
    const int gid  = lane >> 2;       // 0..7
    const int tig  = lane & 3;        // 0..3

    const int bm0 = blockIdx.y * BM;
    const int bn0 = blockIdx.x * BN;

    // ---- tile loader (cp.async), stage st in [0,3) ----
    auto load_tiles = [&](int kt, int st) {
        #pragma unroll
        for (int i = 0; i < 4; i++) {
            int slot = tid + i * 256;          // 1024 float4 slots for A
            int arow = slot >> 3;              // 8 float4 per 32-float row
            int ac4  = slot & 7;
            cp16(smem_u32 + (uint32_t)(st * A_STAGE + arow * ASTRIDE + ac4 * 4) * 4u,
                 X + (size_t)(bm0 + arow) * HIDDEN + kt * BK + ac4 * 4);
        }
        #pragma unroll
        for (int i = 0; i < 4; i++) {
            int slot = tid + i * 256;          // 1024 float4 slots for B
            int brow = slot >> 5;              // 32 float4 per 128-float row
            int bc4  = slot & 31;
            cp16(smem_u32 + (uint32_t)(STAGES * A_STAGE + st * B_STAGE + brow * BSTRIDE + bc4 * 4) * 4u,
                 Bm + (size_t)(kt * BK + brow) * HIDDEN + bn0 + bc4 * 4);
        }
        asm volatile("cp.async.commit_group;");
    };

    float c[4][4][4];
    #pragma unroll
    for (int i = 0; i < 4; i++)
        #pragma unroll
        for (int j = 0; j < 4; j++)
            #pragma unroll
            for (int k = 0; k < 4; k++) c[i][j][k] = 0.f;

    // prologue: 2 stages in flight
    load_tiles(0, 0);
    load_tiles(1, 1);

    int cur = 0;
    for (int kt = 0; kt < NK; kt++) {
        // wait for stage `cur` (groups pending: kt, kt+1)
        if (kt + 2 < NK) {
            asm volatile("cp.async.wait_group 1;");
        } else {
            asm volatile("cp.async.wait_group 0;");
        }
        __syncthreads();   // data of stage cur visible; stage of kt-1 now dead everywhere

        // issue load for kt+2 into the dead slot
        if (kt + 2 < NK) {
            int nst = cur + 2; if (nst >= STAGES) nst -= STAGES;
            load_tiles(kt + 2, nst);
        }

        const uint32_t* as = (const uint32_t*)(smem + cur * A_STAGE);
        const uint32_t* bs = (const uint32_t*)(smem + STAGES * A_STAGE + cur * B_STAGE);

        #pragma unroll
        for (int kk = 0; kk < 4; kk++) {
            const int k0 = kk * 8;
            uint32_t af[4][4], bf[4][2];
            #pragma unroll
            for (int i = 0; i < 4; i++) {
                const int r = wm * 64 + i * 16 + gid;
                af[i][0] = as[(r    ) * ASTRIDE + k0 + tig    ];
                af[i][1] = as[(r + 8) * ASTRIDE + k0 + tig    ];
                af[i][2] = as[(r    ) * ASTRIDE + k0 + tig + 4];
                af[i][3] = as[(r + 8) * ASTRIDE + k0 + tig + 4];
            }
            #pragma unroll
            for (int j = 0; j < 4; j++) {
                const int cc = wn * 32 + j * 8 + gid;
                bf[j][0] = bs[(k0 + tig    ) * BSTRIDE + cc];
                bf[j][1] = bs[(k0 + tig + 4) * BSTRIDE + cc];
            }
            #pragma unroll
            for (int i = 0; i < 4; i++)
                #pragma unroll
                for (int j = 0; j < 4; j++)
                    mma_tf32(c[i][j], af[i], bf[j]);
        }

        cur++; if (cur >= STAGES) cur -= STAGES;
    }

    // ---- fused epilogue: out = DELTA*acc + h*(1+DELTA*a) + DELTA*(hq . p) ----
    #pragma unroll
    for (int i = 0; i < 4; i++) {
        const int r0 = bm0 + wm * 64 + i * 16 + gid;
        const int r1 = r0 + 8;
        const float4 hq0 = *(const float4*)(g_hq + r0 * 4);
        const float4 hq1 = *(const float4*)(g_hq + r1 * 4);
        #pragma unroll
        for (int j = 0; j < 4; j++) {
            const int c0 = bn0 + wn * 32 + j * 8 + 2 * tig;
            const float2 ad = *(const float2*)(Ad + c0);
            const float4 p0 = *(const float4*)(P + (size_t)c0 * 4);
            const float4 p1 = *(const float4*)(P + (size_t)(c0 + 1) * 4);

            const float lr00 = hq0.x * p0.x + hq0.y * p0.y + hq0.z * p0.z + hq0.w * p0.w;
            const float lr01 = hq0.x * p1.x + hq0.y * p1.y + hq0.z * p1.z + hq0.w * p1.w;
            const float lr10 = hq1.x * p0.x + hq1.y * p0.y + hq1.z * p0.z + hq1.w * p0.w;
            const float lr11 = hq1.x * p1.x + hq1.y * p1.y + hq1.z * p1.z + hq1.w * p1.w;

            const float2 h0 = *(const float2*)(H + (size_t)r0 * HIDDEN + c0);
            const float2 h1 = *(const float2*)(H + (size_t)r1 * HIDDEN + c0);

            float2 o0, o1;
            o0.x = DELTA * c[i][j][0] + h0.x * (1.f + DELTA * ad.x) + DELTA * lr00;
            o0.y = DELTA * c[i][j][1] + h0.y * (1.f + DELTA * ad.y) + DELTA * lr01;
            o1.x = DELTA * c[i][j][2] + h1.x * (1.f + DELTA * ad.x) + DELTA * lr10;
            o1.y = DELTA * c[i][j][3] + h1.y * (1.f + DELTA * ad.y) + DELTA * lr11;

            *(float2*)(Out + (size_t)r0 * HIDDEN + c0) = o0;
            *(float2*)(Out + (size_t)r1 * HIDDEN + c0) = o1;
        }
    }
}

// ---------------------------------------------------------------------------
// launch
// ---------------------------------------------------------------------------
extern "C" void kernel_launch(void* const* d_in, const int* in_sizes, int n_in,
                              void* d_out, int out_size) {
    const float* h  = (const float*)d_in[0];   // [BATCH, HIDDEN]
    const float* x  = (const float*)d_in[1];   // [BATCH, HIDDEN]
    const float* a  = (const float*)d_in[2];   // [HIDDEN]
    const float* p  = (const float*)d_in[3];   // [HIDDEN, RANK]
    const float* q  = (const float*)d_in[4];   // [HIDDEN, RANK]
    const float* bm = (const float*)d_in[5];   // [HIDDEN, HIDDEN]
    float* out = (float*)d_out;

    // hq = h @ q   -> g_hq scratch
    hq_kernel<<<BATCH, 256>>>(h, q);

    // fused GEMM + epilogue
    static bool attr_set = false;
    if (!attr_set) {
        cudaFuncSetAttribute(gemm_fused_kernel,
                             cudaFuncAttributeMaxDynamicSharedMemorySize, SMEM_BYTES);
        attr_set = true;
    }
    dim3 grid(HIDDEN / BN, BATCH / BM);  // (32, 32)
    gemm_fused_kernel<<<grid, 256, SMEM_BYTES>>>(x, bm, h, a, p, out);
}

// round 16
// speedup vs baseline: 1.3010x; 1.0004x over previous
#include <cuda_runtime.h>
#include <cuda_bf16.h>
#include <cstdint>

#define HIDDEN 4096
#define RANK   4
#define BATCH  4096
#define DELTA  1.0f

#define BM 128
#define BN 128
#define BK 32
#define NK (HIDDEN / BK)       // 128 k-iterations
#define STAGES 3
#define ASTRIDE 36             // 32 + 4 pad  -> conflict-free A frag loads
#define BSTRIDE 136            // 128 + 8 pad -> conflict-free B frag loads
#define A_STAGE (BM * ASTRIDE) // 4608 floats
#define B_STAGE (BK * BSTRIDE) // 4352 floats
#define SMEM_FLOATS (STAGES * (A_STAGE + B_STAGE))   // 26880
#define SMEM_BYTES  (SMEM_FLOATS * 4)                // 107520

// scratch for hq = h @ q_vec  [BATCH, RANK]
__device__ float g_hq[BATCH * RANK];

// ---------------------------------------------------------------------------
// helpers
// ---------------------------------------------------------------------------
__device__ __forceinline__ void cp16(uint32_t saddr, const float* g) {
    asm volatile("cp.async.cg.shared.global [%0], [%1], 16;" :: "r"(saddr), "l"(g));
}

// NOTE: no cvt.rna.tf32 — HMMA.TF32 truncates the low mantissa bits of fp32
// register operands in hardware (Triton allow_tf32 relies on the same).
__device__ __forceinline__ void mma_tf32(float* c, const uint32_t* a, const uint32_t* b) {
    asm volatile(
        "mma.sync.aligned.m16n8k8.row.col.f32.tf32.tf32.f32 "
        "{%0,%1,%2,%3}, {%4,%5,%6,%7}, {%8,%9}, {%0,%1,%2,%3};"
        : "+f"(c[0]), "+f"(c[1]), "+f"(c[2]), "+f"(c[3])
        : "r"(a[0]), "r"(a[1]), "r"(a[2]), "r"(a[3]), "r"(b[0]), "r"(b[1]));
}

// ---------------------------------------------------------------------------
// hq[b][r] = sum_n h[b][n] * q[n][r]
// ---------------------------------------------------------------------------
__global__ void __launch_bounds__(256) hq_kernel(const float* __restrict__ H,
                                                 const float* __restrict__ Q) {
    int b = blockIdx.x;
    const float* hr = H + (size_t)b * HIDDEN;
    float a0 = 0.f, a1 = 0.f, a2 = 0.f, a3 = 0.f;
    for (int n = threadIdx.x; n < HIDDEN; n += 256) {
        float hv = __ldg(hr + n);
        float4 qv = __ldg(((const float4*)Q) + n);
        a0 += hv * qv.x; a1 += hv * qv.y; a2 += hv * qv.z; a3 += hv * qv.w;
    }
    #pragma unroll
    for (int off = 16; off; off >>= 1) {
        a0 += __shfl_xor_sync(0xFFFFFFFFu, a0, off);
        a1 += __shfl_xor_sync(0xFFFFFFFFu, a1, off);
        a2 += __shfl_xor_sync(0xFFFFFFFFu, a2, off);
        a3 += __shfl_xor_sync(0xFFFFFFFFu, a3, off);
    }
    __shared__ float red[8][4];
    int wid = threadIdx.x >> 5;
    if ((threadIdx.x & 31) == 0) {
        red[wid][0] = a0; red[wid][1] = a1; red[wid][2] = a2; red[wid][3] = a3;
    }
    __syncthreads();
    if (threadIdx.x < 4) {
        float s = 0.f;
        #pragma unroll
        for (int w = 0; w < 8; w++) s += red[w][threadIdx.x];
        g_hq[b * 4 + threadIdx.x] = s;
    }
}

// ---------------------------------------------------------------------------
// fused GEMM: Out = X @ Bm + H*(1 + DELTA*a) + DELTA*(g_hq @ P^T)
// block tile 128x128x32, 8 warps (2m x 4n), warp tile 64x32,
// m16n8k8 tf32 mma, 3-stage cp.async pipeline, ONE syncthreads per k-tile,
// 2 CTAs/SM.
// ---------------------------------------------------------------------------
__global__ void __launch_bounds__(256, 2) gemm_fused_kernel(
    const float* __restrict__ X, const float* __restrict__ Bm,
    const float* __restrict__ H, const float* __restrict__ Ad,
    const float* __restrict__ P, float* __restrict__ Out)
{
    extern __shared__ float smem[];
    const uint32_t smem_u32 = (uint32_t)__cvta_generic_to_shared(smem);

    const int tid  = threadIdx.x;
    const int lane = tid & 31;
    const int wid  = tid >> 5;
    const int wm   = wid >> 2;        // 0..1   (64 rows each)
    const int wn   = wid & 3;         // 0..3   (32 cols each)
    const int gid  = lane >> 2;       // 0..7
    const int tig  = lane & 3;        // 0..3

    const int bm0 = blockIdx.y * BM;
    const int bn0 = blockIdx.x * BN;

    // ---- tile loader (cp.async), stage st in [0,3) ----
    auto load_tiles = [&](int kt, int st) {
        #pragma unroll
        for (int i = 0; i < 4; i++) {
            int slot = tid + i * 256;          // 1024 float4 slots for A
            int arow = slot >> 3;              // 8 float4 per 32-float row
            int ac4  = slot & 7;
            cp16(smem_u32 + (uint32_t)(st * A_STAGE + arow * ASTRIDE + ac4 * 4) * 4u,
                 X + (size_t)(bm0 + arow) * HIDDEN + kt * BK + ac4 * 4);
        }
        #pragma unroll
        for (int i = 0; i < 4; i++) {
            int slot = tid + i * 256;          // 1024 float4 slots for B
            int brow = slot >> 5;              // 32 float4 per 128-float row
            int bc4  = slot & 31;
            cp16(smem_u32 + (uint32_t)(STAGES * A_STAGE + st * B_STAGE + brow * BSTRIDE + bc4 * 4) * 4u,
                 Bm + (size_t)(kt * BK + brow) * HIDDEN + bn0 + bc4 * 4);
        }
        asm volatile("cp.async.commit_group;");
    };

    float c[4][4][4];
    #pragma unroll
    for (int i = 0; i < 4; i++)
        #pragma unroll
        for (int j = 0; j < 4; j++)
            #pragma unroll
            for (int k = 0; k < 4; k++) c[i][j][k] = 0.f;

    // prologue: 2 stages in flight
    load_tiles(0, 0);
    load_tiles(1, 1);

    int cur = 0;
    for (int kt = 0; kt < NK; kt++) {
        // wait for stage `cur` (groups pending: kt, kt+1)
        if (kt + 2 < NK) {
            asm volatile("cp.async.wait_group 1;");
        } else {
            asm volatile("cp.async.wait_group 0;");
        }
        __syncthreads();   // data of stage cur visible; stage of kt-1 now dead everywhere

        // issue load for kt+2 into the dead slot
        if (kt + 2 < NK) {
            int nst = cur + 2; if (nst >= STAGES) nst -= STAGES;
            load_tiles(kt + 2, nst);
        }

        const uint32_t* as = (const uint32_t*)(smem + cur * A_STAGE);
        const uint32_t* bs = (const uint32_t*)(smem + STAGES * A_STAGE + cur * B_STAGE);

        #pragma unroll
        for (int kk = 0; kk < 4; kk++) {
            const int k0 = kk * 8;
            uint32_t af[4][4], bf[4][2];
            #pragma unroll
            for (int i = 0; i < 4; i++) {
                const int r = wm * 64 + i * 16 + gid;
                af[i][0] = as[(r    ) * ASTRIDE + k0 + tig    ];
                af[i][1] = as[(r + 8) * ASTRIDE + k0 + tig    ];
                af[i][2] = as[(r    ) * ASTRIDE + k0 + tig + 4];
                af[i][3] = as[(r + 8) * ASTRIDE + k0 + tig + 4];
            }
            #pragma unroll
            for (int j = 0; j < 4; j++) {
                const int cc = wn * 32 + j * 8 + gid;
                bf[j][0] = bs[(k0 + tig    ) * BSTRIDE + cc];
                bf[j][1] = bs[(k0 + tig + 4) * BSTRIDE + cc];
            }
            #pragma unroll
            for (int i = 0; i < 4; i++)
                #pragma unroll
                for (int j = 0; j < 4; j++)
                    mma_tf32(c[i][j], af[i], bf[j]);
        }

        cur++; if (cur >= STAGES) cur -= STAGES;
    }

    // ---- fused epilogue: out = DELTA*acc + h*(1+DELTA*a) + DELTA*(hq . p) ----
    #pragma unroll
    for (int i = 0; i < 4; i++) {
        const int r0 = bm0 + wm * 64 + i * 16 + gid;
        const int r1 = r0 + 8;
        const float4 hq0 = *(const float4*)(g_hq + r0 * 4);
        const float4 hq1 = *(const float4*)(g_hq + r1 * 4);
        #pragma unroll
        for (int j = 0; j < 4; j++) {
            const int c0 = bn0 + wn * 32 + j * 8 + 2 * tig;
            const float2 ad = *(const float2*)(Ad + c0);
            const float4 p0 = *(const float4*)(P + (size_t)c0 * 4);
            const float4 p1 = *(const float4*)(P + (size_t)(c0 + 1) * 4);

            const float lr00 = hq0.x * p0.x + hq0.y * p0.y + hq0.z * p0.z + hq0.w * p0.w;
            const float lr01 = hq0.x * p1.x + hq0.y * p1.y + hq0.z * p1.z + hq0.w * p1.w;
            const float lr10 = hq1.x * p0.x + hq1.y * p0.y + hq1.z * p0.z + hq1.w * p0.w;
            const float lr11 = hq1.x * p1.x + hq1.y * p1.y + hq1.z * p1.z + hq1.w * p1.w;

            const float2 h0 = *(const float2*)(H + (size_t)r0 * HIDDEN + c0);
            const float2 h1 = *(const float2*)(H + (size_t)r1 * HIDDEN + c0);

            float2 o0, o1;
            o0.x = DELTA * c[i][j][0] + h0.x * (1.f + DELTA * ad.x) + DELTA * lr00;
            o0.y = DELTA * c[i][j][1] + h0.y * (1.f + DELTA * ad.y) + DELTA * lr01;
            o1.x = DELTA * c[i][j][2] + h1.x * (1.f + DELTA * ad.x) + DELTA * lr10;
            o1.y = DELTA * c[i][j][3] + h1.y * (1.f + DELTA * ad.y) + DELTA * lr11;

            *(float2*)(Out + (size_t)r0 * HIDDEN + c0) = o0;
            *(float2*)(Out + (size_t)r1 * HIDDEN + c0) = o1;
        }
    }
}

// ---------------------------------------------------------------------------
// launch
// ---------------------------------------------------------------------------
extern "C" void kernel_launch(void* const* d_in, const int* in_sizes, int n_in,
                              void* d_out, int out_size) {
    const float* h  = (const float*)d_in[0];   // [BATCH, HIDDEN]
    const float* x  = (const float*)d_in[1];   // [BATCH, HIDDEN]
    const float* a  = (const float*)d_in[2];   // [HIDDEN]
    const float* p  = (const float*)d_in[3];   // [HIDDEN, RANK]
    const float* q  = (const float*)d_in[4];   // [HIDDEN, RANK]
    const float* bm = (const float*)d_in[5];   // [HIDDEN, HIDDEN]
    float* out = (float*)d_out;

    // hq = h @ q   -> g_hq scratch
    hq_kernel<<<BATCH, 256>>>(h, q);

    // fused GEMM + epilogue
    static bool attr_set = false;
    if (!attr_set) {
        cudaFuncSetAttribute(gemm_fused_kernel,
                             cudaFuncAttributeMaxDynamicSharedMemorySize, SMEM_BYTES);
        attr_set = true;
    }
    dim3 grid(HIDDEN / BN, BATCH / BM);  // (32, 32)
    gemm_fused_kernel<<<grid, 256, SMEM_BYTES>>>(x, bm, h, a, p, out);
}